// round 6
// baseline (speedup 1.0000x reference)
#include <cuda_runtime.h>
#include <cuda_bf16.h>
#include <math.h>
#include <stdint.h>

#define BATCH    32768
#define DIM      256
#define MAX_IT   40
#define NCTAS    512               // (BATCH/128) * (DIM/128)
#define EW_GRID  (BATCH*DIM/4/256)

// smem stage layout (bytes)
#define A_STRIDE 80                // 40 bf16 per row
#define W_STRIDE 272               // 136 bf16 per row
#define OFF_A0   0
#define OFF_A1   10240
#define OFF_W0   20480
#define OFF_W1   29184
#define STAGE    37888
#define SMEM_TOT (2*STAGE)         // 75776

// ---------------- device scratch ----------------
__device__ float g_x[2][BATCH*DIM];                   // fp32 x ping-pong
__device__ __nv_bfloat16 g_ya0[2][BATCH*DIM];         // y hi split, ping-pong
__device__ __nv_bfloat16 g_ya1[2][BATCH*DIM];         // y lo split
__device__ float g_b[BATCH*DIM];
__device__ float g_WU[DIM*DIM];                       // U^T for bias GEMM
__device__ __nv_bfloat16 g_w0[DIM*DIM];               // Weff hi split [k][n]
__device__ __nv_bfloat16 g_w1[DIM*DIM];               // Weff lo split
__device__ float g_partial[NCTAS*2];
__device__ int   g_active;

// ---------------- helpers ----------------
__device__ __forceinline__ uint32_t sptr(const void* p) {
    return (uint32_t)__cvta_generic_to_shared(p);
}
__device__ __forceinline__ uint32_t bpack(__nv_bfloat16 a, __nv_bfloat16 b) {
    uint16_t ua = *(uint16_t*)&a, ub = *(uint16_t*)&b;
    return (uint32_t)ua | ((uint32_t)ub << 16);
}
__device__ __forceinline__ void cpa16(uint32_t dst, const void* src) {
    asm volatile("cp.async.cg.shared.global [%0], [%1], 16;"
                 :: "r"(dst), "l"(src) : "memory");
}
__device__ __forceinline__ void cpa_commit() {
    asm volatile("cp.async.commit_group;" ::: "memory");
}
template<int N>
__device__ __forceinline__ void cpa_wait() {
    asm volatile("cp.async.wait_group %0;" :: "n"(N) : "memory");
}
__device__ __forceinline__ void ldm_x4(uint32_t* r, uint32_t addr) {
    asm volatile("ldmatrix.sync.aligned.m8n8.x4.shared.b16 {%0,%1,%2,%3}, [%4];"
                 : "=r"(r[0]), "=r"(r[1]), "=r"(r[2]), "=r"(r[3]) : "r"(addr));
}
__device__ __forceinline__ void ldm_x4t(uint32_t* r, uint32_t addr) {
    asm volatile("ldmatrix.sync.aligned.m8n8.x4.trans.shared.b16 {%0,%1,%2,%3}, [%4];"
                 : "=r"(r[0]), "=r"(r[1]), "=r"(r[2]), "=r"(r[3]) : "r"(addr));
}
__device__ __forceinline__ void mma_bf16(float* c, const uint32_t* a, const uint32_t* b) {
    asm volatile(
        "mma.sync.aligned.m16n8k16.row.col.f32.bf16.bf16.f32 "
        "{%0,%1,%2,%3}, {%4,%5,%6,%7}, {%8,%9}, {%0,%1,%2,%3};"
        : "+f"(c[0]), "+f"(c[1]), "+f"(c[2]), "+f"(c[3])
        : "r"(a[0]), "r"(a[1]), "r"(a[2]), "r"(a[3]), "r"(b[0]), "r"(b[1]));
}

// fp32x2 helpers for the bias GEMM
__device__ __forceinline__ unsigned long long pack2(float v) {
    unsigned long long r; unsigned u = __float_as_uint(v);
    asm("mov.b64 %0, {%1, %1};" : "=l"(r) : "r"(u));
    return r;
}
__device__ __forceinline__ void ffma2(unsigned long long& d,
                                      unsigned long long a, unsigned long long b) {
    asm("fma.rn.f32x2 %0, %1, %2, %0;" : "+l"(d) : "l"(a), "l"(b));
}
__device__ __forceinline__ float lo32(unsigned long long v) {
    return __uint_as_float((unsigned)(v & 0xffffffffull));
}
__device__ __forceinline__ float hi32(unsigned long long v) {
    return __uint_as_float((unsigned)(v >> 32));
}

// ---------------- prep: U^T, Weff -> bf16 splits ----------------
__global__ void prep_kernel(const float* __restrict__ U,
                            const float* __restrict__ A,
                            const float* __restrict__ B) {
    int i = blockIdx.x;    // k index (row of Weff)
    int j = threadIdx.x;   // n index (col)
    g_WU[i*DIM + j] = U[j*DIM + i];
    float s = 0.f;
#pragma unroll 8
    for (int p = 0; p < DIM; ++p)
        s = fmaf(A[p*DIM + i], A[p*DIM + j], s);
    float w = -s + B[j*DIM + i] - B[i*DIM + j];
    if (i == j) w += 0.8f;                    // (1-m), m=0.2
    __nv_bfloat16 h0 = __float2bfloat16(w);
    __nv_bfloat16 h1 = __float2bfloat16(w - __bfloat162float(h0));
    g_w0[i*DIM + j] = h0;
    g_w1[i*DIM + j] = h1;
}

__global__ void init_kernel() {
    int i = blockIdx.x * blockDim.x + threadIdx.x;
    ((float4*)g_x[0])[i] = make_float4(0.f, 0.f, 0.f, 0.f);
    ((uint2*)g_ya0[0])[i] = make_uint2(0u, 0u);   // 4 bf16
    ((uint2*)g_ya1[0])[i] = make_uint2(0u, 0u);
    if (i == 0) g_active = 1;
}

// ---------------- bias GEMM (runs once, exact fp32): b = x @ U^T + ub ----------
__launch_bounds__(256, 2)
__global__ void bias_gemm(const float* __restrict__ Ap, const float* __restrict__ ub) {
    __shared__ float As[16][132];
    __shared__ float Bs[16][128];
    const int tid = threadIdx.x;
    const int tx  = tid & 15, ty = tid >> 4;
    const int m0  = blockIdx.y * 128, n0 = blockIdx.x * 128;
    const int ra = tid >> 2, ca = (tid & 3) << 2;
    const int rb = tid >> 5, cb = (tid & 31) << 2;
    unsigned long long acc[8][4];
#pragma unroll
    for (int i = 0; i < 8; ++i)
#pragma unroll
        for (int j = 0; j < 4; ++j) acc[i][j] = 0ull;
    for (int k0 = 0; k0 < DIM; k0 += 16) {
        float4 a0 = *(const float4*)(Ap + (m0 + ra     ) * DIM + k0 + ca);
        float4 a1 = *(const float4*)(Ap + (m0 + ra + 64) * DIM + k0 + ca);
        float4 b0 = *(const float4*)(g_WU + (k0 + rb    ) * DIM + n0 + cb);
        float4 b1 = *(const float4*)(g_WU + (k0 + rb + 8) * DIM + n0 + cb);
        __syncthreads();
        As[ca+0][ra] = a0.x;  As[ca+1][ra] = a0.y;
        As[ca+2][ra] = a0.z;  As[ca+3][ra] = a0.w;
        As[ca+0][ra+64] = a1.x;  As[ca+1][ra+64] = a1.y;
        As[ca+2][ra+64] = a1.z;  As[ca+3][ra+64] = a1.w;
        *(float4*)&Bs[rb  ][cb] = b0;
        *(float4*)&Bs[rb+8][cb] = b1;
        __syncthreads();
#pragma unroll
        for (int kk = 0; kk < 16; ++kk) {
            unsigned long long pb[4], pa[8];
#pragma unroll
            for (int j = 0; j < 4; ++j)
                pb[j] = *(const unsigned long long*)&Bs[kk][tx*2 + j*32];
#pragma unroll
            for (int i = 0; i < 8; ++i) pa[i] = pack2(As[kk][ty*8 + i]);
#pragma unroll
            for (int i = 0; i < 8; ++i)
#pragma unroll
                for (int j = 0; j < 4; ++j) ffma2(acc[i][j], pa[i], pb[j]);
        }
    }
    float2 u[4];
#pragma unroll
    for (int j = 0; j < 4; ++j) u[j] = *(const float2*)(ub + n0 + tx*2 + j*32);
#pragma unroll
    for (int i = 0; i < 8; ++i) {
        float* base = g_b + (m0 + ty*8 + i)*DIM + n0;
#pragma unroll
        for (int j = 0; j < 4; ++j) {
            float2 g;
            g.x = lo32(acc[i][j]) + u[j].x;
            g.y = hi32(acc[i][j]) + u[j].y;
            *(float2*)(base + tx*2 + j*32) = g;
        }
    }
}

// ---------------- iteration kernel: cp.async-pipelined split-bf16 MMA ---------
// G[128,128] = a0@w0 + a1@w0 + a0@w1 (fp32 accum), then fused epilogue:
//   fn = relu(G+b) -> out; err partials from (y, fn);
//   x' = relu(0.5*(y+G+b)); y' = x' + beta*(x'-x) stored as bf16 hi/lo splits
__global__ void __launch_bounds__(256, 2)
iter_kernel(float beta, int par, float* __restrict__ outp) {
    if (g_active == 0) return;
    extern __shared__ __align__(16) unsigned char sm[];
    const uint32_t sb = sptr(sm);

    const int tid  = threadIdx.x;
    const int lane = tid & 31;
    const int wid  = tid >> 5;
    const int wm   = wid & 3;      // warp M index (32 rows each)
    const int wn   = wid >> 2;     // warp N index (64 cols each)
    const int m0   = blockIdx.y * 128;
    const int n0   = blockIdx.x * 128;

    const __nv_bfloat16* __restrict__ ya0 = g_ya0[par];
    const __nv_bfloat16* __restrict__ ya1 = g_ya1[par];

    float acc[2][8][4];
#pragma unroll
    for (int mi = 0; mi < 2; ++mi)
#pragma unroll
        for (int ni = 0; ni < 8; ++ni)
#pragma unroll
            for (int q = 0; q < 4; ++q) acc[mi][ni][q] = 0.f;

    // cp.async index precompute
    const int arow = tid >> 2, aseg = tid & 3;          // A: 128 rows x 4 segs
    const int wrow = tid >> 4, wseg = tid & 15;         // W: 32 rows x 16 segs

    // ldmatrix lane addresses (same layout as R5)
    const uint32_t aoff = (uint32_t)(((wm*32 + (lane & 15)) * 40 + (lane >> 4) * 8) * 2);
    const uint32_t boff = (uint32_t)(((((lane >> 3) & 1) * 8 + (lane & 7)) * 136
                                      + wn*64 + (lane >> 4) * 8) * 2);

    auto issue = [&](int kc, int st) {
        const uint32_t base = sb + st * STAGE;
#pragma unroll
        for (int p = 0; p < 2; ++p) {
            int row = arow + p*64, seg = aseg;
            uint32_t d = base + row*A_STRIDE + seg*16;
            size_t s = (size_t)(m0 + row) * DIM + kc*32 + seg*8;
            cpa16(d + OFF_A0, ya0 + s);
            cpa16(d + OFF_A1, ya1 + s);
        }
#pragma unroll
        for (int p = 0; p < 2; ++p) {
            int row = wrow + p*16, seg = wseg;
            uint32_t d = base + row*W_STRIDE + seg*16;
            size_t s = (size_t)(kc*32 + row) * DIM + n0 + seg*8;
            cpa16(d + OFF_W0, g_w0 + s);
            cpa16(d + OFF_W1, g_w1 + s);
        }
        cpa_commit();
    };

    issue(0, 0);
    for (int kc = 0; kc < 8; ++kc) {
        if (kc < 7) { issue(kc + 1, (kc + 1) & 1); cpa_wait<1>(); }
        else        { cpa_wait<0>(); }
        __syncthreads();
        const uint32_t stb = sb + (kc & 1) * STAGE;
        const uint32_t a0addr = stb + OFF_A0 + aoff;
        const uint32_t a1addr = stb + OFF_A1 + aoff;
        const uint32_t w0addr = stb + OFF_W0 + boff;
        const uint32_t w1addr = stb + OFF_W1 + boff;
#pragma unroll
        for (int kk2 = 0; kk2 < 2; ++kk2) {
            const uint32_t akb = (uint32_t)(kk2 * 16 * 2);
            const uint32_t bkb = (uint32_t)(kk2 * 16 * W_STRIDE);
            uint32_t a0f[2][4], a1f[2][4];
            ldm_x4(a0f[0], a0addr + akb);
            ldm_x4(a0f[1], a0addr + akb + 16*A_STRIDE);
            ldm_x4(a1f[0], a1addr + akb);
            ldm_x4(a1f[1], a1addr + akb + 16*A_STRIDE);
            uint32_t bf[8][2];
#pragma unroll
            for (int nb = 0; nb < 4; ++nb) {
                uint32_t r[4];
                ldm_x4t(r, w0addr + bkb + nb*16*2);
                bf[nb*2  ][0] = r[0];  bf[nb*2  ][1] = r[1];
                bf[nb*2+1][0] = r[2];  bf[nb*2+1][1] = r[3];
            }
#pragma unroll
            for (int mi = 0; mi < 2; ++mi)
#pragma unroll
                for (int ni = 0; ni < 8; ++ni)
                    mma_bf16(acc[mi][ni], a0f[mi], bf[ni]);
#pragma unroll
            for (int mi = 0; mi < 2; ++mi)
#pragma unroll
                for (int ni = 0; ni < 8; ++ni)
                    mma_bf16(acc[mi][ni], a1f[mi], bf[ni]);
#pragma unroll
            for (int nb = 0; nb < 4; ++nb) {
                uint32_t r[4];
                ldm_x4t(r, w1addr + bkb + nb*16*2);
                bf[nb*2  ][0] = r[0];  bf[nb*2  ][1] = r[1];
                bf[nb*2+1][0] = r[2];  bf[nb*2+1][1] = r[3];
            }
#pragma unroll
            for (int mi = 0; mi < 2; ++mi)
#pragma unroll
                for (int ni = 0; ni < 8; ++ni)
                    mma_bf16(acc[mi][ni], a0f[mi], bf[ni]);
        }
        __syncthreads();   // buffer kc&1 free for chunk kc+2
    }

    // --- fused epilogue at fragment positions ---
    const float* __restrict__ xr = g_x[par];
    float* __restrict__ xw = g_x[par ^ 1];
    __nv_bfloat16* __restrict__ y0w = g_ya0[par ^ 1];
    __nv_bfloat16* __restrict__ y1w = g_ya1[par ^ 1];
    float sn = 0.f, sd = 0.f;
#pragma unroll
    for (int mi = 0; mi < 2; ++mi) {
#pragma unroll
        for (int h = 0; h < 2; ++h) {
            int row = m0 + wm*32 + mi*16 + (lane >> 2) + h*8;
#pragma unroll
            for (int ni = 0; ni < 8; ++ni) {
                int col = n0 + wn*64 + ni*8 + (lane & 3)*2;
                int gi = row * DIM + col;
                float g0 = acc[mi][ni][h*2], g1 = acc[mi][ni][h*2 + 1];
                float2 bv = *(const float2*)(g_b + gi);
                float2 xv = *(const float2*)(xr + gi);
                __nv_bfloat162 yh = *(const __nv_bfloat162*)(ya0 + gi);
                __nv_bfloat162 yl = *(const __nv_bfloat162*)(ya1 + gi);
                float yv0 = __bfloat162float(yh.x) + __bfloat162float(yl.x);
                float yv1 = __bfloat162float(yh.y) + __bfloat162float(yl.y);
                float2 fn, xn;
                fn.x = fmaxf(g0 + bv.x, 0.f);
                fn.y = fmaxf(g1 + bv.y, 0.f);
                float d0 = yv0 - fn.x, d1 = yv1 - fn.y;
                sn = fmaf(d0, d0, sn);    sn = fmaf(d1, d1, sn);
                sd = fmaf(yv0, yv0, sd);  sd = fmaf(yv1, yv1, sd);
                xn.x = fmaxf(0.5f*(yv0 + g0 + bv.x), 0.f);
                xn.y = fmaxf(0.5f*(yv1 + g1 + bv.y), 0.f);
                float yn0 = xn.x + beta*(xn.x - xv.x);
                float yn1 = xn.y + beta*(xn.y - xv.y);
                *(float2*)(outp + gi) = fn;
                *(float2*)(xw + gi)   = xn;
                __nv_bfloat16 h0 = __float2bfloat16(yn0);
                __nv_bfloat16 h1 = __float2bfloat16(yn1);
                __nv_bfloat16 l0 = __float2bfloat16(yn0 - __bfloat162float(h0));
                __nv_bfloat16 l1 = __float2bfloat16(yn1 - __bfloat162float(h1));
                *(uint32_t*)(y0w + gi) = bpack(h0, h1);
                *(uint32_t*)(y1w + gi) = bpack(l0, l1);
            }
        }
    }

    // deterministic block reduction
    __syncthreads();
    float* red = (float*)sm;
    red[tid] = sn;  red[256 + tid] = sd;
    __syncthreads();
#pragma unroll
    for (int s = 128; s > 0; s >>= 1) {
        if (tid < s) { red[tid] += red[tid + s]; red[256 + tid] += red[256 + tid + s]; }
        __syncthreads();
    }
    if (tid == 0) {
        int bid = blockIdx.y * 2 + blockIdx.x;
        g_partial[bid*2    ] = red[0];
        g_partial[bid*2 + 1] = red[256];
    }
}

// ---------------- convergence check ----------------
__global__ void check_kernel() {
    if (g_active == 0) return;
    __shared__ float sn[256], sd[256];
    int t = threadIdx.x;
    float a = g_partial[2*t      ] + g_partial[2*(t + 256)    ];
    float b = g_partial[2*t + 1  ] + g_partial[2*(t + 256) + 1];
    sn[t] = a; sd[t] = b;
    __syncthreads();
#pragma unroll
    for (int s = 128; s > 0; s >>= 1) {
        if (t < s) { sn[t] += sn[t + s]; sd[t] += sd[t + s]; }
        __syncthreads();
    }
    if (t == 0) {
        float err = sqrtf(sn[0]) / (1e-6f + sqrtf(sd[0]));
        if (!(err > 1e-4f)) g_active = 0;
    }
}

// ---------------- launch ----------------
extern "C" void kernel_launch(void* const* d_in, const int* in_sizes, int n_in,
                              void* d_out, int out_size) {
    const float* x  = (const float*)d_in[0];
    const float* U  = (const float*)d_in[1];
    const float* ub = (const float*)d_in[2];
    const float* A  = (const float*)d_in[3];
    const float* B  = (const float*)d_in[4];
    (void)in_sizes; (void)n_in; (void)out_size;

    cudaFuncSetAttribute(iter_kernel,
                         cudaFuncAttributeMaxDynamicSharedMemorySize, SMEM_TOT);

    prep_kernel<<<DIM, DIM>>>(U, A, B);
    init_kernel<<<EW_GRID, 256>>>();

    dim3 bgrid(2, 256);
    bias_gemm<<<bgrid, 256>>>(x, ub);

    // kernel i: forward of body i + fn/err of body i-1 (gating validated R1/R2/R5)
    dim3 igrid(2, 256);
    float t = 1.0f;
    for (int i = 1; i <= MAX_IT + 1; ++i) {
        float tn   = 0.5f * (1.0f + sqrtf(1.0f + 4.0f * t * t));
        float beta = (t - 1.0f) / tn;
        iter_kernel<<<igrid, 256, SMEM_TOT>>>(beta, (i - 1) & 1, (float*)d_out);
        if (i <= MAX_IT) check_kernel<<<1, 256>>>();
        t = tn;
    }
}